// round 1
// baseline (speedup 1.0000x reference)
#include <cuda_runtime.h>

// mask scratch (allocation-free rule: __device__ global)
__device__ float g_mask[1024];

#define DIM 1024

// One block, 1024 threads: softmax over mask_param, scaled by DIM * _mask.
__global__ void softmax_mask_kernel(const float* __restrict__ mask_param,
                                    const float* __restrict__ mvec,
                                    float* __restrict__ out_mask_tail) {
    __shared__ float red[32];
    int t = threadIdx.x;
    float v = mask_param[t];

    // max reduce
    float m = v;
    #pragma unroll
    for (int o = 16; o; o >>= 1) m = fmaxf(m, __shfl_xor_sync(0xFFFFFFFFu, m, o));
    if ((t & 31) == 0) red[t >> 5] = m;
    __syncthreads();
    float maxv = red[0];
    #pragma unroll
    for (int i = 1; i < 32; i++) maxv = fmaxf(maxv, red[i]);

    float e = expf(v - maxv);

    // sum reduce
    float s = e;
    #pragma unroll
    for (int o = 16; o; o >>= 1) s += __shfl_xor_sync(0xFFFFFFFFu, s, o);
    __syncthreads();
    if ((t & 31) == 0) red[t >> 5] = s;
    __syncthreads();
    float sum = 0.f;
    #pragma unroll
    for (int i = 0; i < 32; i++) sum += red[i];

    // PRUNE_RATE = 1.0
    float mk = (float)DIM * e / sum * mvec[t];
    g_mask[t] = mk;
    out_mask_tail[t] = mk;
}

// Streaming broadcast multiply: out[i] = x[i] * mask[i % DIM], float4-vectorized.
__global__ void mul_kernel(const float4* __restrict__ x, float4* __restrict__ out,
                           int n4) {
    int idx = blockIdx.x * blockDim.x + threadIdx.x;
    if (idx >= n4) return;
    const float4* mask4 = (const float4*)g_mask;
    float4 mv = __ldg(&mask4[idx & (DIM / 4 - 1)]);
    float4 v = x[idx];
    v.x *= mv.x; v.y *= mv.y; v.z *= mv.z; v.w *= mv.w;
    out[idx] = v;
}

extern "C" void kernel_launch(void* const* d_in, const int* in_sizes, int n_in,
                              void* d_out, int out_size) {
    const float* x          = (const float*)d_in[0];  // [8,4096,1024] fp32
    const float* mask_param = (const float*)d_in[1];  // [1024]
    const float* mvec       = (const float*)d_in[2];  // [1024], all ones

    float* out = (float*)d_out;
    int n = in_sizes[0];            // 33554432
    float* out_mask_tail = out + n; // mask goes after xm

    softmax_mask_kernel<<<1, DIM>>>(mask_param, mvec, out_mask_tail);

    int n4 = n / 4;                 // 8388608
    int threads = 256;
    int blocks = (n4 + threads - 1) / threads;
    mul_kernel<<<blocks, threads>>>((const float4*)x, (float4*)out, n4);
}

// round 2
// speedup vs baseline: 1.0088x; 1.0088x over previous
#include <cuda_runtime.h>

#define DIM 1024
#define TPB 256          // thread t owns float4 column t of each 1024-float row
#define ROW_UNROLL 4
#define GRID 2048

__global__ __launch_bounds__(TPB) void fused_mask_mul_kernel(
    const float4* __restrict__ x4,
    const float4* __restrict__ mask_param4,
    const float4* __restrict__ mvec4,
    float4* __restrict__ out4,
    int nrows)                      // nrows = n / 1024
{
    const int t = threadIdx.x;
    __shared__ float red[8];        // 8 warps per block

    // ---- per-block softmax recompute (4 KB, L2-resident, ~free) ----
    float4 p = mask_param4[t];

    // block max
    float m = fmaxf(fmaxf(p.x, p.y), fmaxf(p.z, p.w));
    #pragma unroll
    for (int o = 16; o; o >>= 1) m = fmaxf(m, __shfl_xor_sync(0xFFFFFFFFu, m, o));
    if ((t & 31) == 0) red[t >> 5] = m;
    __syncthreads();
    float maxv = red[0];
    #pragma unroll
    for (int i = 1; i < 8; i++) maxv = fmaxf(maxv, red[i]);
    __syncthreads();

    float e0 = __expf(p.x - maxv);
    float e1 = __expf(p.y - maxv);
    float e2 = __expf(p.z - maxv);
    float e3 = __expf(p.w - maxv);

    // block sum
    float s = e0 + e1 + e2 + e3;
    #pragma unroll
    for (int o = 16; o; o >>= 1) s += __shfl_xor_sync(0xFFFFFFFFu, s, o);
    if ((t & 31) == 0) red[t >> 5] = s;
    __syncthreads();
    float sum = 0.f;
    #pragma unroll
    for (int i = 0; i < 8; i++) sum += red[i];

    float4 mv = mvec4[t];
    float inv = (float)DIM / sum;   // PRUNE_RATE = 1.0
    float4 mk;
    mk.x = e0 * inv * mv.x;
    mk.y = e1 * inv * mv.y;
    mk.z = e2 * inv * mv.z;
    mk.w = e3 * inv * mv.w;

    // mask tail: out[n .. n+1023], written once by block 0
    if (blockIdx.x == 0)
        out4[(size_t)nrows * (DIM / 4) + t] = mk;

    // ---- streaming multiply: thread t = column t, mask in registers ----
    size_t base = (size_t)blockIdx.x * ROW_UNROLL * (DIM / 4) + t;
    const size_t stride = (size_t)gridDim.x * ROW_UNROLL * (DIM / 4);
    int row = blockIdx.x * ROW_UNROLL;

    for (; row + ROW_UNROLL <= nrows; row += gridDim.x * ROW_UNROLL, base += stride) {
        float4 v0 = x4[base + 0 * (DIM / 4)];
        float4 v1 = x4[base + 1 * (DIM / 4)];
        float4 v2 = x4[base + 2 * (DIM / 4)];
        float4 v3 = x4[base + 3 * (DIM / 4)];
        v0.x *= mk.x; v0.y *= mk.y; v0.z *= mk.z; v0.w *= mk.w;
        v1.x *= mk.x; v1.y *= mk.y; v1.z *= mk.z; v1.w *= mk.w;
        v2.x *= mk.x; v2.y *= mk.y; v2.z *= mk.z; v2.w *= mk.w;
        v3.x *= mk.x; v3.y *= mk.y; v3.z *= mk.z; v3.w *= mk.w;
        out4[base + 0 * (DIM / 4)] = v0;
        out4[base + 1 * (DIM / 4)] = v1;
        out4[base + 2 * (DIM / 4)] = v2;
        out4[base + 3 * (DIM / 4)] = v3;
    }
    // remainder rows (nrows=32768 divides evenly for the bench shape, but be safe)
    for (; row < nrows; row++, base += (DIM / 4)) {
        float4 v = x4[base];
        v.x *= mk.x; v.y *= mk.y; v.z *= mk.z; v.w *= mk.w;
        out4[base] = v;
    }
}

extern "C" void kernel_launch(void* const* d_in, const int* in_sizes, int n_in,
                              void* d_out, int out_size) {
    const float* x          = (const float*)d_in[0];  // [8,4096,1024] fp32
    const float* mask_param = (const float*)d_in[1];  // [1024]
    const float* mvec       = (const float*)d_in[2];  // [1024]

    int n = in_sizes[0];
    int nrows = n / DIM;

    fused_mask_mul_kernel<<<GRID, TPB>>>(
        (const float4*)x, (const float4*)mask_param, (const float4*)mvec,
        (float4*)d_out, nrows);
}

// round 3
// speedup vs baseline: 1.0443x; 1.0351x over previous
#include <cuda_runtime.h>

#define DIM 1024
#define TPB 256          // thread t owns float4 column t of each 1024-float row
#define ROW_UNROLL 8
#define GRID 2048        // 2048 * 8 = 16384 rows/sweep; 32768 rows -> 2 sweeps

__global__ __launch_bounds__(TPB) void fused_mask_mul_kernel(
    const float4* __restrict__ x4,
    const float4* __restrict__ mask_param4,
    const float4* __restrict__ mvec4,
    float4* __restrict__ out4,
    int nrows)                      // nrows = n / 1024
{
    const int t = threadIdx.x;
    __shared__ float red[8];        // 8 warps per block

    // ---- per-block softmax recompute (4 KB, L2-resident, ~free) ----
    float4 p = mask_param4[t];

    float m = fmaxf(fmaxf(p.x, p.y), fmaxf(p.z, p.w));
    #pragma unroll
    for (int o = 16; o; o >>= 1) m = fmaxf(m, __shfl_xor_sync(0xFFFFFFFFu, m, o));
    if ((t & 31) == 0) red[t >> 5] = m;
    __syncthreads();
    float maxv = red[0];
    #pragma unroll
    for (int i = 1; i < 8; i++) maxv = fmaxf(maxv, red[i]);
    __syncthreads();

    float e0 = __expf(p.x - maxv);
    float e1 = __expf(p.y - maxv);
    float e2 = __expf(p.z - maxv);
    float e3 = __expf(p.w - maxv);

    float s = e0 + e1 + e2 + e3;
    #pragma unroll
    for (int o = 16; o; o >>= 1) s += __shfl_xor_sync(0xFFFFFFFFu, s, o);
    if ((t & 31) == 0) red[t >> 5] = s;
    __syncthreads();
    float sum = 0.f;
    #pragma unroll
    for (int i = 0; i < 8; i++) sum += red[i];

    float4 mv = mvec4[t];
    float inv = (float)DIM / sum;   // PRUNE_RATE = 1.0
    float4 mk;
    mk.x = e0 * inv * mv.x;
    mk.y = e1 * inv * mv.y;
    mk.z = e2 * inv * mv.z;
    mk.w = e3 * inv * mv.w;

    // mask tail: out[n .. n+1023], written once by block 0
    if (blockIdx.x == 0)
        out4[(size_t)nrows * (DIM / 4) + t] = mk;

    // ---- streaming multiply: thread t = column t, mask in registers ----
    // 8-row batch, evict-first loads + streaming stores (no reuse either way).
    size_t base = (size_t)blockIdx.x * ROW_UNROLL * (DIM / 4) + t;
    const size_t stride = (size_t)gridDim.x * ROW_UNROLL * (DIM / 4);
    int row = blockIdx.x * ROW_UNROLL;

    for (; row + ROW_UNROLL <= nrows; row += gridDim.x * ROW_UNROLL, base += stride) {
        float4 v[ROW_UNROLL];
        #pragma unroll
        for (int r = 0; r < ROW_UNROLL; r++)
            v[r] = __ldcs(&x4[base + (size_t)r * (DIM / 4)]);
        #pragma unroll
        for (int r = 0; r < ROW_UNROLL; r++) {
            v[r].x *= mk.x; v[r].y *= mk.y; v[r].z *= mk.z; v[r].w *= mk.w;
        }
        #pragma unroll
        for (int r = 0; r < ROW_UNROLL; r++)
            __stcs(&out4[base + (size_t)r * (DIM / 4)], v[r]);
    }
    // remainder rows (bench shape divides evenly, but be safe)
    for (; row < nrows; row++, base += (DIM / 4)) {
        float4 v = __ldcs(&x4[base]);
        v.x *= mk.x; v.y *= mk.y; v.z *= mk.z; v.w *= mk.w;
        __stcs(&out4[base], v);
    }
}

extern "C" void kernel_launch(void* const* d_in, const int* in_sizes, int n_in,
                              void* d_out, int out_size) {
    const float* x          = (const float*)d_in[0];  // [8,4096,1024] fp32
    const float* mask_param = (const float*)d_in[1];  // [1024]
    const float* mvec       = (const float*)d_in[2];  // [1024]

    int n = in_sizes[0];
    int nrows = n / DIM;

    fused_mask_mul_kernel<<<GRID, TPB>>>(
        (const float4*)x, (const float4*)mask_param, (const float4*)mvec,
        (float4*)d_out, nrows);
}